// round 12
// baseline (speedup 1.0000x reference)
#include <cuda_runtime.h>
#include <cuda_fp16.h>

// Problem constants
#define FX 80
#define NX 128
#define HH 512
#define WW 1024
#define BC 16                 // B*C fused channel count
#define M  (FX * NX * NX)     // 1310720 texels per channel
#define HW (HH * WW)          // 524288 pixels

// Scratch: x transposed + converted to fp16, layout [M][16] halfs (32B/texel).
// 40MB -> goal: keep DIRTY-RESIDENT in L2 (126MB) until the sample pass reads
// it, deferring its DRAM write-back out of the transpose's critical path.
__device__ __align__(128) __half g_xt[(size_t)M * BC];

__device__ __forceinline__ unsigned int h2u(__half2 h) {
    return *reinterpret_cast<unsigned int*>(&h);
}

// ---------------------------------------------------------------------------
// Pass 1: fused transpose+convert, register-only scalar (measured-best shape).
// Input reads use __ldlu (LAST-USE): every x element is read exactly once in
// the whole program, so mark its lines for immediate eviction. This is the
// stronger form of the R11 .cs hint (which measured -2.3us): minimizes the
// 80MB read stream's L2 footprint so the freshly-written dirty table lines
// survive in L2 and their 40MB write-back stays out of this kernel's window.
// ---------------------------------------------------------------------------
__global__ void __launch_bounds__(256) transpose_kernel(const float* __restrict__ x) {
    const int m = blockIdx.x * 256 + threadIdx.x;   // one texel per thread

    float v[16];
#pragma unroll
    for (int c = 0; c < 16; c++)
        v[c] = __ldlu(x + (size_t)c * M + m);       // 16 coalesced last-use LDG.32

    unsigned int w[8];
#pragma unroll
    for (int j = 0; j < 8; j++)
        w[j] = h2u(__floats2half2_rn(v[2 * j], v[2 * j + 1]));

    uint4* dst = reinterpret_cast<uint4*>(g_xt + (size_t)m * BC);
    dst[0] = make_uint4(w[0], w[1], w[2], w[3]);
    dst[1] = make_uint4(w[4], w[5], w[6], w[7]);
}

// accumulate 8 fp16 channels (one uint4) into fp32 accumulators with weight w
__device__ __forceinline__ void acc8(float* r, const uint4& a, float w) {
    const __half2* h = reinterpret_cast<const __half2*>(&a);
#pragma unroll
    for (int j = 0; j < 4; j++) {
        float2 f = __half22float2(h[j]);
        r[2 * j]     = fmaf(f.x, w, r[2 * j]);
        r[2 * j + 1] = fmaf(f.y, w, r[2 * j + 1]);
    }
}

// ---------------------------------------------------------------------------
// Pass 2: bilinear gather — R9 exact (measured floor 17.6-18.1us across six
// shape variants). Block = 256 threads = 128 pixels x 2 half-groups; 4
// independent LDG.128 per thread (16B = 8 fp16 channels per corner); direct
// 64B-coalesced stores per plane. No smem, no barriers.
// ---------------------------------------------------------------------------
__global__ void __launch_bounds__(256) sample_kernel(const int*   __restrict__ quad,
                                                     const float* __restrict__ uv,
                                                     float*       __restrict__ out) {
    const int t   = threadIdx.x;
    const int p   = t >> 1;            // pixel-in-tile 0..127
    const int hg  = t & 1;             // half-group: channels hg*8 .. hg*8+7
    const int pix = blockIdx.x * 128 + p;

    const float2 uvp = reinterpret_cast<const float2*>(uv)[pix];
    const int    f   = quad[pix];

    int u0 = min(max((int)floorf(uvp.x), 0), NX - 2);
    int v0 = min(max((int)floorf(uvp.y), 0), NX - 2);
    const float du = uvp.x - (float)u0;
    const float dv = uvp.y - (float)v0;

    const __half* base = g_xt + ((size_t)((f * NX + v0) * NX + u0)) * BC + hg * 8;
    const uint4 a00 = *reinterpret_cast<const uint4*>(base);
    const uint4 a01 = *reinterpret_cast<const uint4*>(base + BC);
    const uint4 a10 = *reinterpret_cast<const uint4*>(base + BC * NX);
    const uint4 a11 = *reinterpret_cast<const uint4*>(base + BC * NX + BC);

    const float w00 = (1.0f - du) * (1.0f - dv);
    const float w01 = du * (1.0f - dv);
    const float w10 = (1.0f - du) * dv;
    const float w11 = du * dv;

    float r[8];
#pragma unroll
    for (int j = 0; j < 8; j++) r[j] = 0.0f;
    acc8(r, a00, w00);
    acc8(r, a01, w01);
    acc8(r, a10, w10);
    acc8(r, a11, w11);

    // direct coalesced stores: 16 lanes of same hg -> 16 consecutive pixels
    float* o = out + (size_t)(hg * 8) * HW + pix;
#pragma unroll
    for (int k = 0; k < 8; k++)
        o[(size_t)k * HW] = r[k];
}

extern "C" void kernel_launch(void* const* d_in, const int* in_sizes, int n_in,
                              void* d_out, int out_size) {
    const float* x    = (const float*)d_in[0];   // [2,8,80,128,128] fp32
    const int*   quad = (const int*)  d_in[1];   // [512,1024] int32
    const float* uv   = (const float*)d_in[2];   // [512,1024,2] fp32
    float*       out  = (float*)d_out;           // [2,8,512,1024] fp32

    transpose_kernel<<<M / 256, 256>>>(x);            // 5120 blocks
    sample_kernel<<<HW / 128, 256>>>(quad, uv, out);  // 4096 blocks
}